// round 16
// baseline (speedup 1.0000x reference)
#include <cuda_runtime.h>
#include <math.h>

#define NN  32768
#define EE  524288
#define BB  32
#define K1c 512
#define K2c 256
#define BK1 16384
#define BK2 8192
#define FH  128
#define SCAN_NB 64

// ---------------- scratch ----------------
__device__ float g_t[NN*FH];
__device__ float g_h1[NN*FH];
__device__ float g_a[NN*FH];
__device__ float g_bf[NN*FH];
__device__ float g_xout[NN*FH];
__device__ float g_xoutF[NN*FH];
__device__ float g_mA[NN*FH];
__device__ float g_mB[NN*64];
__device__ float g_xp1[BK1*FH];
__device__ float g_t2[BK1*FH];
__device__ float g_h2[BK1*FH];
__device__ float g_xp2[BK2*FH];
__device__ float g_sc1[NN];
__device__ float g_sc2[BK1];
__device__ float g_deggt[NN];
__device__ float g_xdeg[NN];
__device__ float g_dinv1[NN], g_invd1[NN];
__device__ float g_dinv2[BK1], g_invd2[BK1];
__device__ int   g_cntD[NN], g_cntS[NN], g_cur1[NN];
__device__ int   g_row1[NN+1];
__device__ int   g_csr1[EE];
__device__ int   g_cnt2[BK1], g_cur2[BK1];
__device__ int   g_row2[BK1+1];
__device__ int   g_csr2[EE];
__device__ int   g_perm1[BK1], g_pos1[NN];
__device__ int   g_perm2[BK2], g_pos2[BK1];
__device__ float g_g1[BB*256], g_g2[BB*256];
__device__ int   g_bsum[SCAN_NB];

// ---------------- helpers ----------------
__device__ __forceinline__ unsigned long long fma2_(unsigned long long a, unsigned long long b,
                                                    unsigned long long c) {
    unsigned long long d;
    asm("fma.rn.f32x2 %0, %1, %2, %3;" : "=l"(d) : "l"(a), "l"(b), "l"(c));
    return d;
}
__device__ __forceinline__ unsigned long long mul2_(unsigned long long a, unsigned long long b) {
    unsigned long long d;
    asm("mul.rn.f32x2 %0, %1, %2;" : "=l"(d) : "l"(a), "l"(b));
    return d;
}
__device__ __forceinline__ unsigned long long add2_(unsigned long long a, unsigned long long b) {
    unsigned long long d;
    asm("add.rn.f32x2 %0, %1, %2;" : "=l"(d) : "l"(a), "l"(b));
    return d;
}
__device__ __forceinline__ unsigned long long dup2_(float x) {
    unsigned long long d;
    asm("mov.b64 %0, {%1, %1};" : "=l"(d) : "f"(x));
    return d;
}
__device__ __forceinline__ unsigned long long pack2_(float lo, float hi) {
    unsigned long long d;
    asm("mov.b64 %0, {%1, %2};" : "=l"(d) : "f"(lo), "f"(hi));
    return d;
}
__device__ __forceinline__ void unpack2_(unsigned long long v, float& lo, float& hi) {
    asm("mov.b64 {%0, %1}, %2;" : "=f"(lo), "=f"(hi) : "l"(v));
}
__device__ __forceinline__ unsigned tf32_(float x) {
    unsigned r;
    asm("cvt.rna.tf32.f32 %0, %1;" : "=r"(r) : "f"(x));
    return r;
}

// ---------------- XLA:CPU f32 tanh ----------------
__device__ __forceinline__ float xla_tanhf(float x) {
    const float kMax = 7.90531110763549805f;
    float xc = fminf(fmaxf(x, -kMax), kMax);
    float x2 = __fmul_rn(xc, xc);
    float p = fmaf(x2, -2.76076847742355e-16f, 2.00018790482477e-13f);
    p = fmaf(x2, p, -8.60467152213735e-11f);
    p = fmaf(x2, p, 5.12229709037114e-08f);
    p = fmaf(x2, p, 1.48572235717979e-05f);
    p = fmaf(x2, p, 6.37261928875436e-04f);
    p = fmaf(x2, p, 4.89352455891786e-03f);
    p = __fmul_rn(p, xc);
    float q = fmaf(x2, 1.19825839466702e-06f, 1.18534705686654e-04f);
    q = fmaf(x2, q, 2.26843463243900e-03f);
    q = fmaf(x2, q, 4.89352518554385e-03f);
    float r = __fdiv_rn(p, q);
    if (fabsf(x) < 0.0004f) r = x;
    return r;
}

// ---------------- graph prep ----------------

__global__ void zero_counts_kernel() {
    int i = blockIdx.x * blockDim.x + threadIdx.x;
    if (i < NN) { g_cntD[i] = 0; g_cntS[i] = 0; g_cur1[i] = 0; }
    if (i < BK1) { g_cnt2[i] = 0; g_cur2[i] = 0; }
}

__global__ void count_kernel(const int* __restrict__ src, const int* __restrict__ dst) {
    int e = blockIdx.x * blockDim.x + threadIdx.x;
    if (e >= EE) return;
    atomicAdd(&g_cntD[dst[e]], 1);
    atomicAdd(&g_cntS[src[e]], 1);
}

__global__ void scan_p1_kernel(const int* __restrict__ cnt, int n) {
    int per = n / SCAN_NB;
    int base = blockIdx.x * per;
    int tid = threadIdx.x;
    int lane = tid & 31, wid = tid >> 5;
    int s = 0;
    for (int i = tid; i < per; i += 256) s += cnt[base + i];
#pragma unroll
    for (int o = 16; o > 0; o >>= 1) s += __shfl_down_sync(0xffffffffu, s, o);
    __shared__ int ws[8];
    if (lane == 0) ws[wid] = s;
    __syncthreads();
    if (tid == 0) {
        int t = 0;
#pragma unroll
        for (int i = 0; i < 8; i++) t += ws[i];
        g_bsum[blockIdx.x] = t;
    }
}
// scan_p3 with inlined p2 (each block locally prefixes g_bsum) + fused degprep
__global__ void scan_p3_kernel(const int* __restrict__ cnt, int* __restrict__ row, int n, int mode) {
    __shared__ int bo[SCAN_NB + 1];
    int per = n / SCAN_NB;
    int ch = per >> 8;
    int base = blockIdx.x * per;
    int tid = threadIdx.x;
    int lane = tid & 31, wid = tid >> 5;
    if (tid == 0) {
        int run = 0;
        for (int i = 0; i < SCAN_NB; i++) { bo[i] = run; run += g_bsum[i]; }
        bo[SCAN_NB] = run;
    }
    int vals[2] = {0, 0};
    int t0 = tid * ch;
    for (int i = 0; i < ch; i++) vals[i] = cnt[base + t0 + i];
    int tot = vals[0] + vals[1];
    int sc = tot;
#pragma unroll
    for (int o = 1; o < 32; o <<= 1) {
        int u = __shfl_up_sync(0xffffffffu, sc, o);
        if (lane >= o) sc += u;
    }
    __shared__ int ws[8];
    if (lane == 31) ws[wid] = sc;
    __syncthreads();
    int woff = 0;
    for (int i = 0; i < wid; i++) woff += ws[i];
    int run = bo[blockIdx.x] + woff + (sc - tot);
    for (int i = 0; i < ch; i++) {
        int idx = base + t0 + i;
        row[idx] = run; run += vals[i];
        float d = __fadd_rn(1.0f, (float)vals[i]);
        if (mode == 1) {
            g_dinv1[idx] = __fdiv_rn(1.0f, __fsqrt_rn(d));
            g_invd1[idx] = __fdiv_rn(1.0f, d);
            g_deggt[idx] = (float)g_cntS[idx];
        } else {
            g_dinv2[idx] = __fdiv_rn(1.0f, __fsqrt_rn(d));
            g_invd2[idx] = __fdiv_rn(1.0f, d);
        }
    }
    if (blockIdx.x == SCAN_NB - 1 && tid == 255) row[n] = bo[SCAN_NB];
}

__global__ void fill1_kernel(const int* __restrict__ src, const int* __restrict__ dst) {
    int e = blockIdx.x * blockDim.x + threadIdx.x;
    if (e >= EE) return;
    int d = dst[e];
    int slot = g_row1[d] + atomicAdd(&g_cur1[d], 1);
    g_csr1[slot] = e;
}

__global__ void count2_kernel(const int* __restrict__ src, const int* __restrict__ dst) {
    int e = blockIdx.x * blockDim.x + threadIdx.x;
    if (e >= EE) return;
    int ns = g_pos1[src[e]];
    int nd = g_pos1[dst[e]];
    if (ns >= 0 && nd >= 0) atomicAdd(&g_cnt2[nd], 1);
}

__global__ void fill2_kernel(const int* __restrict__ src, const int* __restrict__ dst) {
    int e = blockIdx.x * blockDim.x + threadIdx.x;
    if (e >= EE) return;
    int ns = g_pos1[src[e]];
    int nd = g_pos1[dst[e]];
    if (ns >= 0 && nd >= 0) {
        int slot = g_row2[nd] + atomicAdd(&g_cur2[nd], 1);
        g_csr2[slot] = e;
    }
}

__global__ void sortmap_kernel(const int* __restrict__ row, int* __restrict__ csr,
                               const int* __restrict__ src, int n, int mode) {
    int warp = (blockIdx.x * blockDim.x + threadIdx.x) >> 5;
    int lane = threadIdx.x & 31;
    if (warp >= n) return;
    int beg = row[warp], end = row[warp + 1], deg = end - beg;
    if (deg <= 32) {
        int val = (lane < deg) ? csr[beg + lane] : 0x7fffffff;
#pragma unroll
        for (int k = 2; k <= 32; k <<= 1) {
#pragma unroll
            for (int j = k >> 1; j > 0; j >>= 1) {
                int p = __shfl_xor_sync(0xffffffffu, val, j);
                bool dirUp = ((lane & k) == 0);
                bool lower = ((lane & j) == 0);
                int mn = min(val, p), mx = max(val, p);
                val = (dirUp == lower) ? mn : mx;
            }
        }
        if (lane < deg) {
            int id = val;
            csr[beg + lane] = (mode == 1) ? src[id] : g_pos1[src[id]];
        }
    } else if (lane == 0) {
        if (deg <= 96) {
            int buf[96];
            for (int i = 0; i < deg; i++) buf[i] = csr[beg + i];
            for (int i = 1; i < deg; i++) {
                int key = buf[i];
                int j = i - 1;
                while (j >= 0 && buf[j] > key) { buf[j + 1] = buf[j]; j--; }
                buf[j + 1] = key;
            }
            for (int i = 0; i < deg; i++) {
                int id = buf[i];
                csr[beg + i] = (mode == 1) ? src[id] : g_pos1[src[id]];
            }
        } else {
            for (int i = beg + 1; i < end; i++) {
                int key = csr[i];
                int j = i - 1;
                while (j >= beg && csr[j] > key) { csr[j + 1] = csr[j]; j--; }
                csr[j + 1] = key;
            }
            for (int i = beg; i < end; i++) {
                int id = csr[i];
                csr[i] = (mode == 1) ? src[id] : g_pos1[src[id]];
            }
        }
    }
}

// ---------------- bitwise fp32 matmul (score path: c1, c2) ----------------
template<int FOUT>
__global__ void __launch_bounds__(256, 4)
mm_kernel(const float* __restrict__ A, const float* __restrict__ W,
          const float* __restrict__ bias, float* __restrict__ C, int act) {
    constexpr int CP = FOUT / 32;
    constexpr int NP2 = CP / 2;
    __shared__ float As[32][32];
    __shared__ float Ws[32][FOUT];
    const int tid = threadIdx.x;
    const int rg = tid >> 5;
    const int lane = tid & 31;
    const int m0 = blockIdx.x * 32;

    unsigned long long accA2[4][NP2], accB2[4][NP2];
#pragma unroll
    for (int r = 0; r < 4; r++)
#pragma unroll
        for (int c = 0; c < NP2; c++) { accA2[r][c] = 0ull; accB2[r][c] = 0ull; }

    for (int kc = 0; kc < 128; kc += 32) {
        {
            int r = tid >> 3, q = tid & 7;
            ((float4*)(&As[r][0]))[q] = ((const float4*)(A + (size_t)(m0 + r) * 128 + kc))[q];
        }
        for (int i = tid; i < 32 * FOUT / 4; i += 256) {
            int r = i / (FOUT / 4), q = i % (FOUT / 4);
            ((float4*)(&Ws[r][0]))[q] = ((const float4*)(W + (size_t)(kc + r) * FOUT))[q];
        }
        __syncthreads();
#pragma unroll
        for (int k = 0; k < 32; k += 4) {
            float4 a4[4];
#pragma unroll
            for (int r = 0; r < 4; r++) a4[r] = *(const float4*)&As[rg * 4 + r][k];
#pragma unroll
            for (int kk = 0; kk < 4; kk++) {
                unsigned long long wp[NP2];
                if constexpr (CP == 4) {
                    float4 w4 = *(const float4*)&Ws[k + kk][lane * 4];
                    wp[0] = pack2_(w4.x, w4.y);
                    wp[1] = pack2_(w4.z, w4.w);
                } else {
                    float2 w2 = *(const float2*)&Ws[k + kk][lane * 2];
                    wp[0] = pack2_(w2.x, w2.y);
                }
#pragma unroll
                for (int r = 0; r < 4; r++) {
                    unsigned long long av2 = dup2_((&a4[r].x)[kk]);
                    if ((kk & 1) == 0) {
#pragma unroll
                        for (int c = 0; c < NP2; c++) accA2[r][c] = fma2_(av2, wp[c], accA2[r][c]);
                    } else {
#pragma unroll
                        for (int c = 0; c < NP2; c++) accB2[r][c] = fma2_(av2, wp[c], accB2[r][c]);
                    }
                }
            }
        }
        __syncthreads();
    }

#pragma unroll
    for (int r = 0; r < 4; r++) {
        int row = m0 + rg * 4 + r;
#pragma unroll
        for (int cp = 0; cp < NP2; cp++) {
            float aLo, aHi, bLo, bHi;
            unpack2_(accA2[r][cp], aLo, aHi);
            unpack2_(accB2[r][cp], bLo, bHi);
            float v0 = __fadd_rn(aLo, bLo);
            float v1 = __fadd_rn(aHi, bHi);
            int c0 = cp * 2, c1 = cp * 2 + 1;
            if (bias != nullptr) {
                v0 = __fadd_rn(v0, bias[lane * CP + c0]);
                v1 = __fadd_rn(v1, bias[lane * CP + c1]);
            }
            if (act == 1) { v0 = fmaxf(v0, 0.0f); v1 = fmaxf(v1, 0.0f); }
            else if (act == 2) { v0 = xla_tanhf(v0); v1 = xla_tanhf(v1); }
            C[(size_t)row * FOUT + lane * CP + c0] = v0;
            C[(size_t)row * FOUT + lane * CP + c1] = v1;
        }
    }
}

// ---------------- TF32 tensor-core matmul (tolerance-bound paths) ----------------
template<int FOUT>
__global__ void tmm_kernel(const float* __restrict__ A, const float* __restrict__ W,
                           const float* __restrict__ bias, float* __restrict__ C, int act) {
    constexpr int NT = FOUT / 16;
    __shared__ float As[64][36];
    __shared__ float Ws[32][FOUT + 4];
    const int tid = threadIdx.x;
    const int warp = tid >> 5, lane = tid & 31;
    const int wr = warp & 3;
    const int wc = warp >> 2;
    const int m0 = blockIdx.x * 64;
    const int mrow = wr * 16;
    const int n0 = wc * (FOUT / 2);
    const int gq = lane >> 2, tg = lane & 3;

    float acc[NT][4];
#pragma unroll
    for (int t = 0; t < NT; t++)
#pragma unroll
        for (int i = 0; i < 4; i++) acc[t][i] = 0.0f;

    for (int kc = 0; kc < 128; kc += 32) {
        for (int i = tid; i < 512; i += 256) {
            int r = i >> 3, q = i & 7;
            float4 v = *(const float4*)(A + (size_t)(m0 + r) * 128 + kc + q * 4);
            As[r][q * 4 + 0] = v.x; As[r][q * 4 + 1] = v.y;
            As[r][q * 4 + 2] = v.z; As[r][q * 4 + 3] = v.w;
        }
        for (int i = tid; i < 32 * FOUT / 4; i += 256) {
            int r = i / (FOUT / 4), q = i % (FOUT / 4);
            float4 v = *(const float4*)(W + (size_t)(kc + r) * FOUT + q * 4);
            Ws[r][q * 4 + 0] = v.x; Ws[r][q * 4 + 1] = v.y;
            Ws[r][q * 4 + 2] = v.z; Ws[r][q * 4 + 3] = v.w;
        }
        __syncthreads();
#pragma unroll
        for (int k8 = 0; k8 < 32; k8 += 8) {
            unsigned a0 = tf32_(As[mrow + gq][k8 + tg]);
            unsigned a1 = tf32_(As[mrow + gq + 8][k8 + tg]);
            unsigned a2 = tf32_(As[mrow + gq][k8 + tg + 4]);
            unsigned a3 = tf32_(As[mrow + gq + 8][k8 + tg + 4]);
#pragma unroll
            for (int t = 0; t < NT; t++) {
                int nb = n0 + t * 8;
                unsigned b0 = tf32_(Ws[k8 + tg][nb + gq]);
                unsigned b1 = tf32_(Ws[k8 + tg + 4][nb + gq]);
                asm volatile(
                    "mma.sync.aligned.m16n8k8.row.col.f32.tf32.tf32.f32 "
                    "{%0,%1,%2,%3}, {%4,%5,%6,%7}, {%8,%9}, {%0,%1,%2,%3};"
                    : "+f"(acc[t][0]), "+f"(acc[t][1]), "+f"(acc[t][2]), "+f"(acc[t][3])
                    : "r"(a0), "r"(a1), "r"(a2), "r"(a3), "r"(b0), "r"(b1));
            }
        }
        __syncthreads();
    }

#pragma unroll
    for (int t = 0; t < NT; t++) {
        int nb = n0 + t * 8 + 2 * tg;
        int r0 = m0 + mrow + gq;
        float v0 = acc[t][0], v1 = acc[t][1], v2 = acc[t][2], v3 = acc[t][3];
        if (bias != nullptr) {
            float b0v = bias[nb], b1v = bias[nb + 1];
            v0 += b0v; v1 += b1v; v2 += b0v; v3 += b1v;
        }
        if (act == 1) {
            v0 = fmaxf(v0, 0.f); v1 = fmaxf(v1, 0.f);
            v2 = fmaxf(v2, 0.f); v3 = fmaxf(v3, 0.f);
        }
        C[(size_t)r0 * FOUT + nb]     = v0;
        C[(size_t)r0 * FOUT + nb + 1] = v1;
        C[(size_t)(r0 + 8) * FOUT + nb]     = v2;
        C[(size_t)(r0 + 8) * FOUT + nb + 1] = v3;
    }
}

// ---------------- GCN aggregation (f32x2-packed; per-feature chains bitwise) ----------------
__global__ void agg_kernel(const float* __restrict__ t, const int* __restrict__ row,
                           const int* __restrict__ csr, const float* __restrict__ dinv,
                           const float* __restrict__ invd, const float* __restrict__ bias,
                           float* __restrict__ out, int n, int act) {
    int v = (blockIdx.x * blockDim.x + threadIdx.x) >> 5;
    int lane = threadIdx.x & 31;
    if (v >= n) return;
    int beg = row[v], end = row[v + 1];
    float dv = dinv[v], iv = invd[v];
    unsigned long long axy = 0ull, azw = 0ull;
#pragma unroll 4
    for (int j = beg; j < end; j++) {
        int s = __ldg(&csr[j]);
        float w = __fmul_rn(__ldg(&dinv[s]), dv);
        unsigned long long w2 = dup2_(w);
        float4 h = *(const float4*)&t[(size_t)s * 128 + lane * 4];
        axy = add2_(axy, mul2_(pack2_(h.x, h.y), w2));
        azw = add2_(azw, mul2_(pack2_(h.z, h.w), w2));
    }
    float ax, ay, az, aw;
    unpack2_(axy, ax, ay);
    unpack2_(azw, az, aw);
    float4 tv = *(const float4*)&t[(size_t)v * 128 + lane * 4];
    float4 b4 = *(const float4*)&bias[lane * 4];
    float o0 = __fadd_rn(__fadd_rn(ax, __fmul_rn(tv.x, iv)), b4.x);
    float o1 = __fadd_rn(__fadd_rn(ay, __fmul_rn(tv.y, iv)), b4.y);
    float o2 = __fadd_rn(__fadd_rn(az, __fmul_rn(tv.z, iv)), b4.z);
    float o3 = __fadd_rn(__fadd_rn(aw, __fmul_rn(tv.w, iv)), b4.w);
    if (act == 1) { o0 = fmaxf(o0, 0.f); o1 = fmaxf(o1, 0.f); o2 = fmaxf(o2, 0.f); o3 = fmaxf(o3, 0.f); }
    else if (act == 2) { o0 = xla_tanhf(o0); o1 = xla_tanhf(o1); o2 = xla_tanhf(o2); o3 = xla_tanhf(o3); }
    *(float4*)&out[(size_t)v * 128 + lane * 4] = make_float4(o0, o1, o2, o3);
}

// ---------------- fused dot + scoreagg + topk (per graph) ----------------
// lin chain: 4 strided fmaf lanes + (l0+l2)+(l1+l3) (exact dot128 replica).
// score chain: sequential ascending-j, mul/add separate (exact scoreagg replica).
template<int NP>
__global__ void topkfused_kernel(const float* __restrict__ h, const int* __restrict__ row,
                                 const int* __restrict__ csr, const float* __restrict__ dinv,
                                 const float* __restrict__ invd, const float* __restrict__ wp,
                                 const float* __restrict__ bp,
                                 float* __restrict__ score_out, int* __restrict__ perm,
                                 int* __restrict__ pos, int kkeep, float thr_rel) {
    __shared__ float slin[NP];
    __shared__ float ss[NP];
    __shared__ int   si[NP];
    int b = blockIdx.x, tid = threadIdx.x;
    int base = b * NP;
    // phase 1: lin
    for (int i = tid; i < NP; i += blockDim.x) {
        const float* a = h + (size_t)(base + i) * 128;
        float l0 = 0.f, l1 = 0.f, l2 = 0.f, l3 = 0.f;
#pragma unroll 8
        for (int k = 0; k < 128; k += 4) {
            l0 = fmaf(a[k],     __ldg(&wp[k]),     l0);
            l1 = fmaf(a[k + 1], __ldg(&wp[k + 1]), l1);
            l2 = fmaf(a[k + 2], __ldg(&wp[k + 2]), l2);
            l3 = fmaf(a[k + 3], __ldg(&wp[k + 3]), l3);
        }
        slin[i] = __fadd_rn(__fadd_rn(l0, l2), __fadd_rn(l1, l3));
    }
    __syncthreads();
    // phase 2: score
    float bias0 = bp[0];
    for (int i = tid; i < NP; i += blockDim.x) {
        int v = base + i;
        int beg = row[v], end = row[v + 1];
        float dv = dinv[v];
        float acc = 0.0f;
        for (int j = beg; j < end; j++) {
            int s = csr[j];
            float w = __fmul_rn(dinv[s], dv);
            acc = __fadd_rn(acc, __fmul_rn(slin[s - base], w));
        }
        float sc = __fadd_rn(__fadd_rn(acc, __fmul_rn(slin[i], invd[v])), bias0);
        ss[i] = sc;
        si[i] = i;
        score_out[v] = sc;
        pos[v] = -1;
    }
    __syncthreads();
    // phase 3: bitonic sort desc, exact ties -> lower index
    for (int k = 2; k <= NP; k <<= 1) {
        for (int j = k >> 1; j > 0; j >>= 1) {
            for (int i = tid; i < NP; i += blockDim.x) {
                int ixj = i ^ j;
                if (ixj > i) {
                    float sa = ss[i], sb = ss[ixj];
                    int ia = si[i], ib = si[ixj];
                    bool b_first = (sb > sa) || (sb == sa && ib < ia);
                    bool a_first = (sa > sb) || (sa == sb && ia < ib);
                    bool sw = ((i & k) == 0) ? b_first : a_first;
                    if (sw) { ss[i] = sb; ss[ixj] = sa; si[i] = ib; si[ixj] = ia; }
                }
            }
            __syncthreads();
        }
    }
    if (tid == 0 && thr_rel > 0.0f) {
        for (int pass = 0; pass < 6; pass++) {
            bool any = false;
            for (int p = 0; p < NP - 1; p++) {
                float a = ss[p], c = ss[p + 1];
                if (a > c) {
                    float gap = __fadd_rn(a, -c);
                    float thr = thr_rel * fmaxf(fabsf(a), fabsf(c));
                    if (gap <= thr && si[p] > si[p + 1]) {
                        ss[p] = c; ss[p + 1] = a;
                        int t2 = si[p]; si[p] = si[p + 1]; si[p + 1] = t2;
                        any = true;
                    }
                }
            }
            if (!any) break;
        }
    }
    __syncthreads();
    for (int i = tid; i < kkeep; i += blockDim.x) {
        int g = base + si[i];
        perm[b * kkeep + i] = g;
        pos[g] = b * kkeep + i;
    }
}

// fused gate+unpool level 1: xp1 (compacted) and xout in one h1 pass
__global__ void unpoolgate1_kernel(const float* __restrict__ h, const float* __restrict__ score,
                                   const int* __restrict__ pos, float* __restrict__ xp,
                                   float* __restrict__ out) {
    int gid = blockIdx.x * blockDim.x + threadIdx.x;
    if (gid >= NN * 128) return;
    int v = gid >> 7, c = gid & 127;
    int j = pos[v];
    float val = 0.0f;
    if (j >= 0) {
        val = __fmul_rn(h[gid], xla_tanhf(score[v]));
        xp[(size_t)j * 128 + c] = val;
    }
    out[gid] = val;
}

// fused gate+double-unpool level 2: xp2 (compacted) and xoutF in one pass
__global__ void unpoolgate2_kernel(const float* __restrict__ h2, const float* __restrict__ score2,
                                   float* __restrict__ xp2, float* __restrict__ out) {
    int gid = blockIdx.x * blockDim.x + threadIdx.x;
    if (gid >= NN * 128) return;
    int v = gid >> 7, c = gid & 127;
    int p1 = g_pos1[v];
    float val = 0.0f;
    if (p1 >= 0) {
        int p2 = g_pos2[p1];
        if (p2 >= 0) {
            val = __fmul_rn(h2[(size_t)p1 * 128 + c], xla_tanhf(score2[p1]));
            xp2[(size_t)p2 * 128 + c] = val;
        }
    }
    out[gid] = val;
}

__global__ void pool_stats_kernel(const float* __restrict__ xp, float* __restrict__ g, int kk) {
    int b = blockIdx.x, c = threadIdx.x;
    float mx = -3.402823466e38f, sm = 0.f;
    const float* base = xp + (size_t)b * kk * 128;
    for (int r = 0; r < kk; r++) {
        float v = base[(size_t)r * 128 + c];
        mx = fmaxf(mx, v);
        sm = __fadd_rn(sm, v);
    }
    g[b * 256 + c] = mx;
    g[b * 256 + 128 + c] = __fdiv_rn(sm, (float)kk);
}

__global__ void gather_kernel(const int* __restrict__ perm, float* __restrict__ og,
                              float* __restrict__ op, int cnt) {
    int j = blockIdx.x * blockDim.x + threadIdx.x;
    if (j >= cnt) return;
    int v = perm[j];
    og[j] = g_deggt[v];
    op[j] = g_xdeg[v];
}

__global__ void mlp641_kernel(const float* __restrict__ in, const float* __restrict__ w,
                              const float* __restrict__ bptr, float* __restrict__ out, int M) {
    int v = blockIdx.x * blockDim.x + threadIdx.x;
    if (v >= M) return;
    const float* a = in + (size_t)v * 64;
    float l0 = 0.f, l1 = 0.f, l2 = 0.f, l3 = 0.f;
#pragma unroll
    for (int k = 0; k < 64; k += 4) {
        l0 = fmaf(a[k],     __ldg(&w[k]),     l0);
        l1 = fmaf(a[k + 1], __ldg(&w[k + 1]), l1);
        l2 = fmaf(a[k + 2], __ldg(&w[k + 2]), l2);
        l3 = fmaf(a[k + 3], __ldg(&w[k + 3]), l3);
    }
    float acc = __fadd_rn(__fadd_rn(l0, l2), __fadd_rn(l1, l3));
    acc = __fadd_rn(acc, bptr[0]);
    out[v] = fmaxf(acc, 0.f);
}

__global__ void head_kernel(const float* __restrict__ wl1, const float* __restrict__ bl1,
                            const float* __restrict__ wl2, const float* __restrict__ bl2,
                            const float* __restrict__ wl3, const float* __restrict__ bl3,
                            float* __restrict__ ocls) {
    __shared__ float gg[256];
    __shared__ float ga[128];
    __shared__ float gb[64];
    int b = blockIdx.x, t = threadIdx.x;
    gg[t]       = g_g1[b * 256 + t]       + g_g2[b * 256 + t];
    gg[t + 128] = g_g1[b * 256 + 128 + t] + g_g2[b * 256 + 128 + t];
    __syncthreads();
    float acc = 0.0f;
    for (int k = 0; k < 256; k++) acc = fmaf(gg[k], wl1[k * 128 + t], acc);
    ga[t] = fmaxf(acc + bl1[t], 0.f);
    __syncthreads();
    if (t < 64) {
        float a2 = 0.0f;
        for (int k = 0; k < 128; k++) a2 = fmaf(ga[k], wl2[k * 64 + t], a2);
        gb[t] = fmaxf(a2 + bl2[t], 0.f);
    }
    __syncthreads();
    if (t < 10) {
        float a3 = 0.0f;
        for (int k = 0; k < 64; k++) a3 = fmaf(gb[k], wl3[k * 10 + t], a3);
        ocls[b * 10 + t] = a3 + bl3[t];
    }
}

// ---------------- host ----------------
static void* devp(const void* sym) {
    void* p = nullptr;
    cudaGetSymbolAddress(&p, sym);
    return p;
}

extern "C" void kernel_launch(void* const* d_in, const int* in_sizes, int n_in,
                              void* d_out, int out_size) {
    const float* x     = (const float*)d_in[0];
    const int*   esrc  = (const int*)d_in[1];
    const int*   edst  = (const int*)d_in[2];
    const float* w_c1 = (const float*)d_in[3];  const float* b_c1 = (const float*)d_in[4];
    const float* w_c2 = (const float*)d_in[5];  const float* b_c2 = (const float*)d_in[6];
    const float* w_c3 = (const float*)d_in[7];  const float* b_c3 = (const float*)d_in[8];
    const float* w_c4 = (const float*)d_in[9];  const float* b_c4 = (const float*)d_in[10];
    const float* w_c5 = (const float*)d_in[11]; const float* b_c5 = (const float*)d_in[12];
    const float* w_p1 = (const float*)d_in[13]; const float* b_p1 = (const float*)d_in[14];
    const float* w_p2 = (const float*)d_in[15]; const float* b_p2 = (const float*)d_in[16];
    const float* w_l1 = (const float*)d_in[17]; const float* b_l1 = (const float*)d_in[18];
    const float* w_l2 = (const float*)d_in[19]; const float* b_l2 = (const float*)d_in[20];
    const float* w_l3 = (const float*)d_in[21]; const float* b_l3 = (const float*)d_in[22];
    const float* w_l4 = (const float*)d_in[23]; const float* b_l4 = (const float*)d_in[24];
    const float* w_l5 = (const float*)d_in[25]; const float* b_l5 = (const float*)d_in[26];
    const float* w_l6 = (const float*)d_in[27]; const float* b_l6 = (const float*)d_in[28];

    float* out = (float*)d_out;
    float* o_cls  = out;
    float* o_dec1 = out + 320;
    float* o_dec2 = o_dec1 + (size_t)NN * FH;
    float* o_dgt1 = o_dec2 + (size_t)NN * FH;
    float* o_dpr1 = o_dgt1 + BK1;
    float* o_dgt2 = o_dpr1 + BK1;
    float* o_dpr2 = o_dgt2 + BK2;

    float* p_t     = (float*)devp(g_t);
    float* p_h1    = (float*)devp(g_h1);
    float* p_a     = (float*)devp(g_a);
    float* p_bf    = (float*)devp(g_bf);
    float* p_xout  = (float*)devp(g_xout);
    float* p_xoutF = (float*)devp(g_xoutF);
    float* p_mA    = (float*)devp(g_mA);
    float* p_mB    = (float*)devp(g_mB);
    float* p_xp1   = (float*)devp(g_xp1);
    float* p_t2    = (float*)devp(g_t2);
    float* p_h2    = (float*)devp(g_h2);
    float* p_xp2   = (float*)devp(g_xp2);
    float* p_sc1   = (float*)devp(g_sc1);
    float* p_sc2   = (float*)devp(g_sc2);
    float* p_xdeg  = (float*)devp(g_xdeg);
    float* p_dinv1 = (float*)devp(g_dinv1);
    float* p_invd1 = (float*)devp(g_invd1);
    float* p_dinv2 = (float*)devp(g_dinv2);
    float* p_invd2 = (float*)devp(g_invd2);
    int*   p_cntD  = (int*)devp(g_cntD);
    int*   p_row1  = (int*)devp(g_row1);
    int*   p_csr1  = (int*)devp(g_csr1);
    int*   p_cnt2  = (int*)devp(g_cnt2);
    int*   p_row2  = (int*)devp(g_row2);
    int*   p_csr2  = (int*)devp(g_csr2);
    int*   p_perm1 = (int*)devp(g_perm1);
    int*   p_pos1  = (int*)devp(g_pos1);
    int*   p_perm2 = (int*)devp(g_perm2);
    int*   p_pos2  = (int*)devp(g_pos2);
    float* p_g1    = (float*)devp(g_g1);
    float* p_g2    = (float*)devp(g_g2);

    // ---- level 1 prep ----
    zero_counts_kernel<<<NN / 256, 256>>>();
    count_kernel<<<EE / 256, 256>>>(esrc, edst);
    mm_kernel<128><<<NN / 32, 256>>>(x, w_c1, nullptr, p_t, 0);
    scan_p1_kernel<<<SCAN_NB, 256>>>(p_cntD, NN);
    scan_p3_kernel<<<SCAN_NB, 256>>>(p_cntD, p_row1, NN, 1);
    fill1_kernel<<<EE / 256, 256>>>(esrc, edst);
    sortmap_kernel<<<NN / 8, 256>>>(p_row1, p_csr1, esrc, NN, 1);
    agg_kernel<<<NN / 8, 256>>>(p_t, p_row1, p_csr1, p_dinv1, p_invd1, b_c1, p_h1, NN, 1);

    // ---- SAGPool level 1 (fused lin+score+topk; bitwise) ----
    topkfused_kernel<1024><<<BB, 512>>>(p_h1, p_row1, p_csr1, p_dinv1, p_invd1, w_p1, b_p1,
                                        p_sc1, p_perm1, p_pos1, K1c, 6e-7f);
    unpoolgate1_kernel<<<(NN * 128) / 256, 256>>>(p_h1, p_sc1, p_pos1, p_xp1, p_xout);

    // ---- decoder 1 -> o_dec1 (tf32) ----
    tmm_kernel<128><<<NN / 64, 256>>>(p_xout, w_c3, nullptr, p_t, 0);
    agg_kernel<<<NN / 8, 256>>>(p_t, p_row1, p_csr1, p_dinv1, p_invd1, b_c3, p_a, NN, 2);
    tmm_kernel<128><<<NN / 64, 256>>>(p_a, w_c4, nullptr, p_t, 0);
    agg_kernel<<<NN / 8, 256>>>(p_t, p_row1, p_csr1, p_dinv1, p_invd1, b_c4, p_bf, NN, 2);
    tmm_kernel<128><<<NN / 64, 256>>>(p_bf, w_c5, nullptr, p_t, 0);
    agg_kernel<<<NN / 8, 256>>>(p_t, p_row1, p_csr1, p_dinv1, p_invd1, b_c5, o_dec1, NN, 0);

    // ---- degree mlp (tf32) ----
    tmm_kernel<128><<<NN / 64, 256>>>(p_xout, w_l4, b_l4, p_mA, 1);
    tmm_kernel<64><<<NN / 64, 256>>>(p_mA, w_l5, b_l5, p_mB, 1);
    mlp641_kernel<<<NN / 256, 256>>>(p_mB, w_l6, b_l6, p_xdeg, NN);
    gather_kernel<<<BK1 / 256, 256>>>(p_perm1, o_dgt1, o_dpr1, BK1);
    pool_stats_kernel<<<BB, 128>>>(p_xp1, p_g1, K1c);

    // ---- level 2 graph ----
    count2_kernel<<<EE / 256, 256>>>(esrc, edst);
    scan_p1_kernel<<<SCAN_NB, 256>>>(p_cnt2, BK1);
    scan_p3_kernel<<<SCAN_NB, 256>>>(p_cnt2, p_row2, BK1, 2);
    fill2_kernel<<<EE / 256, 256>>>(esrc, edst);
    sortmap_kernel<<<BK1 / 8, 256>>>(p_row2, p_csr2, esrc, BK1, 2);

    // h2 = relu(gcn(xp1, w_c2)) (bitwise)
    mm_kernel<128><<<BK1 / 32, 256>>>(p_xp1, w_c2, nullptr, p_t2, 0);
    agg_kernel<<<BK1 / 8, 256>>>(p_t2, p_row2, p_csr2, p_dinv2, p_invd2, b_c2, p_h2, BK1, 1);

    // ---- SAGPool level 2 (fused; bitwise, no near-tie canon) ----
    topkfused_kernel<512><<<BB, 512>>>(p_h2, p_row2, p_csr2, p_dinv2, p_invd2, w_p2, b_p2,
                                       p_sc2, p_perm2, p_pos2, K2c, 0.0f);
    unpoolgate2_kernel<<<(NN * 128) / 256, 256>>>(p_h2, p_sc2, p_xp2, p_xoutF);
    gather_kernel<<<BK2 / 256, 256>>>(p_perm2, o_dgt2, o_dpr2, BK2);
    pool_stats_kernel<<<BB, 128>>>(p_xp2, p_g2, K2c);

    // ---- decoder 2 -> o_dec2 (tf32) ----
    tmm_kernel<128><<<NN / 64, 256>>>(p_xoutF, w_c3, nullptr, p_t, 0);
    agg_kernel<<<NN / 8, 256>>>(p_t, p_row1, p_csr1, p_dinv1, p_invd1, b_c3, p_a, NN, 2);
    tmm_kernel<128><<<NN / 64, 256>>>(p_a, w_c4, nullptr, p_t, 0);
    agg_kernel<<<NN / 8, 256>>>(p_t, p_row1, p_csr1, p_dinv1, p_invd1, b_c4, p_bf, NN, 2);
    tmm_kernel<128><<<NN / 64, 256>>>(p_bf, w_c5, nullptr, p_t, 0);
    agg_kernel<<<NN / 8, 256>>>(p_t, p_row1, p_csr1, p_dinv1, p_invd1, b_c5, o_dec2, NN, 0);

    // ---- classification head ----
    head_kernel<<<BB, 128>>>(w_l1, b_l1, w_l2, b_l2, w_l3, b_l3, o_cls);
}

// round 17
// speedup vs baseline: 1.1004x; 1.1004x over previous
#include <cuda_runtime.h>
#include <math.h>

#define NN  32768
#define EE  524288
#define BB  32
#define K1c 512
#define K2c 256
#define BK1 16384
#define BK2 8192
#define FH  128
#define SCAN_NB 64

// ---------------- scratch ----------------
__device__ float g_t[NN*FH];
__device__ float g_h1[NN*FH];
__device__ float g_a[NN*FH];
__device__ float g_bf[NN*FH];
__device__ float g_xout[NN*FH];
__device__ float g_xoutF[NN*FH];
__device__ float g_mA[NN*FH];
__device__ float g_mB[NN*64];
__device__ float g_xp1[BK1*FH];
__device__ float g_t2[BK1*FH];
__device__ float g_h2[BK1*FH];
__device__ float g_xp2[BK2*FH];
__device__ float g_lin[NN];
__device__ float g_sc1[NN];
__device__ float g_sc2[BK1];
__device__ float g_deggt[NN];
__device__ float g_xdeg[NN];
__device__ float g_dinv1[NN], g_invd1[NN];
__device__ float g_dinv2[BK1], g_invd2[BK1];
__device__ int   g_cntD[NN], g_cntS[NN], g_cur1[NN];
__device__ int   g_row1[NN+1];
__device__ int   g_csr1[EE];
__device__ int   g_cnt2[BK1], g_cur2[BK1];
__device__ int   g_row2[BK1+1];
__device__ int   g_csr2[EE];
__device__ int   g_perm1[BK1], g_pos1[NN];
__device__ int   g_perm2[BK2], g_pos2[BK1];
__device__ float g_g1[BB*256], g_g2[BB*256];
__device__ int   g_bsum[SCAN_NB];

// ---------------- helpers ----------------
__device__ __forceinline__ unsigned long long fma2_(unsigned long long a, unsigned long long b,
                                                    unsigned long long c) {
    unsigned long long d;
    asm("fma.rn.f32x2 %0, %1, %2, %3;" : "=l"(d) : "l"(a), "l"(b), "l"(c));
    return d;
}
__device__ __forceinline__ unsigned long long mul2_(unsigned long long a, unsigned long long b) {
    unsigned long long d;
    asm("mul.rn.f32x2 %0, %1, %2;" : "=l"(d) : "l"(a), "l"(b));
    return d;
}
__device__ __forceinline__ unsigned long long add2_(unsigned long long a, unsigned long long b) {
    unsigned long long d;
    asm("add.rn.f32x2 %0, %1, %2;" : "=l"(d) : "l"(a), "l"(b));
    return d;
}
__device__ __forceinline__ unsigned long long dup2_(float x) {
    unsigned long long d;
    asm("mov.b64 %0, {%1, %1};" : "=l"(d) : "f"(x));
    return d;
}
__device__ __forceinline__ unsigned long long pack2_(float lo, float hi) {
    unsigned long long d;
    asm("mov.b64 %0, {%1, %2};" : "=l"(d) : "f"(lo), "f"(hi));
    return d;
}
__device__ __forceinline__ void unpack2_(unsigned long long v, float& lo, float& hi) {
    asm("mov.b64 {%0, %1}, %2;" : "=f"(lo), "=f"(hi) : "l"(v));
}
__device__ __forceinline__ unsigned tf32_(float x) {
    unsigned r;
    asm("cvt.rna.tf32.f32 %0, %1;" : "=r"(r) : "f"(x));
    return r;
}

// ---------------- XLA:CPU f32 tanh ----------------
__device__ __forceinline__ float xla_tanhf(float x) {
    const float kMax = 7.90531110763549805f;
    float xc = fminf(fmaxf(x, -kMax), kMax);
    float x2 = __fmul_rn(xc, xc);
    float p = fmaf(x2, -2.76076847742355e-16f, 2.00018790482477e-13f);
    p = fmaf(x2, p, -8.60467152213735e-11f);
    p = fmaf(x2, p, 5.12229709037114e-08f);
    p = fmaf(x2, p, 1.48572235717979e-05f);
    p = fmaf(x2, p, 6.37261928875436e-04f);
    p = fmaf(x2, p, 4.89352455891786e-03f);
    p = __fmul_rn(p, xc);
    float q = fmaf(x2, 1.19825839466702e-06f, 1.18534705686654e-04f);
    q = fmaf(x2, q, 2.26843463243900e-03f);
    q = fmaf(x2, q, 4.89352518554385e-03f);
    float r = __fdiv_rn(p, q);
    if (fabsf(x) < 0.0004f) r = x;
    return r;
}

// ---------------- graph prep ----------------

__global__ void zero_counts_kernel() {
    int i = blockIdx.x * blockDim.x + threadIdx.x;
    if (i < NN) { g_cntD[i] = 0; g_cntS[i] = 0; g_cur1[i] = 0; }
    if (i < BK1) { g_cnt2[i] = 0; g_cur2[i] = 0; }
}

__global__ void count_kernel(const int* __restrict__ src, const int* __restrict__ dst) {
    int e = blockIdx.x * blockDim.x + threadIdx.x;
    if (e >= EE) return;
    atomicAdd(&g_cntD[dst[e]], 1);
    atomicAdd(&g_cntS[src[e]], 1);
}

__global__ void scan_p1_kernel(const int* __restrict__ cnt, int n) {
    int per = n / SCAN_NB;
    int base = blockIdx.x * per;
    int tid = threadIdx.x;
    int lane = tid & 31, wid = tid >> 5;
    int s = 0;
    for (int i = tid; i < per; i += 256) s += cnt[base + i];
#pragma unroll
    for (int o = 16; o > 0; o >>= 1) s += __shfl_down_sync(0xffffffffu, s, o);
    __shared__ int ws[8];
    if (lane == 0) ws[wid] = s;
    __syncthreads();
    if (tid == 0) {
        int t = 0;
#pragma unroll
        for (int i = 0; i < 8; i++) t += ws[i];
        g_bsum[blockIdx.x] = t;
    }
}
// scan_p3 with inlined p2 + fused degprep
__global__ void scan_p3_kernel(const int* __restrict__ cnt, int* __restrict__ row, int n, int mode) {
    __shared__ int bo[SCAN_NB + 1];
    int per = n / SCAN_NB;
    int ch = per >> 8;
    int base = blockIdx.x * per;
    int tid = threadIdx.x;
    int lane = tid & 31, wid = tid >> 5;
    if (tid == 0) {
        int run = 0;
        for (int i = 0; i < SCAN_NB; i++) { bo[i] = run; run += g_bsum[i]; }
        bo[SCAN_NB] = run;
    }
    int vals[2] = {0, 0};
    int t0 = tid * ch;
    for (int i = 0; i < ch; i++) vals[i] = cnt[base + t0 + i];
    int tot = vals[0] + vals[1];
    int sc = tot;
#pragma unroll
    for (int o = 1; o < 32; o <<= 1) {
        int u = __shfl_up_sync(0xffffffffu, sc, o);
        if (lane >= o) sc += u;
    }
    __shared__ int ws[8];
    if (lane == 31) ws[wid] = sc;
    __syncthreads();
    int woff = 0;
    for (int i = 0; i < wid; i++) woff += ws[i];
    int run = bo[blockIdx.x] + woff + (sc - tot);
    for (int i = 0; i < ch; i++) {
        int idx = base + t0 + i;
        row[idx] = run; run += vals[i];
        float d = __fadd_rn(1.0f, (float)vals[i]);
        if (mode == 1) {
            g_dinv1[idx] = __fdiv_rn(1.0f, __fsqrt_rn(d));
            g_invd1[idx] = __fdiv_rn(1.0f, d);
            g_deggt[idx] = (float)g_cntS[idx];
        } else {
            g_dinv2[idx] = __fdiv_rn(1.0f, __fsqrt_rn(d));
            g_invd2[idx] = __fdiv_rn(1.0f, d);
        }
    }
    if (blockIdx.x == SCAN_NB - 1 && tid == 255) row[n] = bo[SCAN_NB];
}

__global__ void fill1_kernel(const int* __restrict__ src, const int* __restrict__ dst) {
    int e = blockIdx.x * blockDim.x + threadIdx.x;
    if (e >= EE) return;
    int d = dst[e];
    int slot = g_row1[d] + atomicAdd(&g_cur1[d], 1);
    g_csr1[slot] = e;
}

__global__ void count2_kernel(const int* __restrict__ src, const int* __restrict__ dst) {
    int e = blockIdx.x * blockDim.x + threadIdx.x;
    if (e >= EE) return;
    int ns = g_pos1[src[e]];
    int nd = g_pos1[dst[e]];
    if (ns >= 0 && nd >= 0) atomicAdd(&g_cnt2[nd], 1);
}

__global__ void fill2_kernel(const int* __restrict__ src, const int* __restrict__ dst) {
    int e = blockIdx.x * blockDim.x + threadIdx.x;
    if (e >= EE) return;
    int ns = g_pos1[src[e]];
    int nd = g_pos1[dst[e]];
    if (ns >= 0 && nd >= 0) {
        int slot = g_row2[nd] + atomicAdd(&g_cur2[nd], 1);
        g_csr2[slot] = e;
    }
}

__global__ void sortmap_kernel(const int* __restrict__ row, int* __restrict__ csr,
                               const int* __restrict__ src, int n, int mode) {
    int warp = (blockIdx.x * blockDim.x + threadIdx.x) >> 5;
    int lane = threadIdx.x & 31;
    if (warp >= n) return;
    int beg = row[warp], end = row[warp + 1], deg = end - beg;
    if (deg <= 32) {
        int val = (lane < deg) ? csr[beg + lane] : 0x7fffffff;
#pragma unroll
        for (int k = 2; k <= 32; k <<= 1) {
#pragma unroll
            for (int j = k >> 1; j > 0; j >>= 1) {
                int p = __shfl_xor_sync(0xffffffffu, val, j);
                bool dirUp = ((lane & k) == 0);
                bool lower = ((lane & j) == 0);
                int mn = min(val, p), mx = max(val, p);
                val = (dirUp == lower) ? mn : mx;
            }
        }
        if (lane < deg) {
            int id = val;
            csr[beg + lane] = (mode == 1) ? src[id] : g_pos1[src[id]];
        }
    } else if (lane == 0) {
        if (deg <= 96) {
            int buf[96];
            for (int i = 0; i < deg; i++) buf[i] = csr[beg + i];
            for (int i = 1; i < deg; i++) {
                int key = buf[i];
                int j = i - 1;
                while (j >= 0 && buf[j] > key) { buf[j + 1] = buf[j]; j--; }
                buf[j + 1] = key;
            }
            for (int i = 0; i < deg; i++) {
                int id = buf[i];
                csr[beg + i] = (mode == 1) ? src[id] : g_pos1[src[id]];
            }
        } else {
            for (int i = beg + 1; i < end; i++) {
                int key = csr[i];
                int j = i - 1;
                while (j >= beg && csr[j] > key) { csr[j + 1] = csr[j]; j--; }
                csr[j + 1] = key;
            }
            for (int i = beg; i < end; i++) {
                int id = csr[i];
                csr[i] = (mode == 1) ? src[id] : g_pos1[src[id]];
            }
        }
    }
}

// ---------------- bitwise fp32 matmul (score path: c1, c2) ----------------
template<int FOUT>
__global__ void __launch_bounds__(256, 4)
mm_kernel(const float* __restrict__ A, const float* __restrict__ W,
          const float* __restrict__ bias, float* __restrict__ C, int act) {
    constexpr int CP = FOUT / 32;
    constexpr int NP2 = CP / 2;
    __shared__ float As[32][32];
    __shared__ float Ws[32][FOUT];
    const int tid = threadIdx.x;
    const int rg = tid >> 5;
    const int lane = tid & 31;
    const int m0 = blockIdx.x * 32;

    unsigned long long accA2[4][NP2], accB2[4][NP2];
#pragma unroll
    for (int r = 0; r < 4; r++)
#pragma unroll
        for (int c = 0; c < NP2; c++) { accA2[r][c] = 0ull; accB2[r][c] = 0ull; }

    for (int kc = 0; kc < 128; kc += 32) {
        {
            int r = tid >> 3, q = tid & 7;
            ((float4*)(&As[r][0]))[q] = ((const float4*)(A + (size_t)(m0 + r) * 128 + kc))[q];
        }
        for (int i = tid; i < 32 * FOUT / 4; i += 256) {
            int r = i / (FOUT / 4), q = i % (FOUT / 4);
            ((float4*)(&Ws[r][0]))[q] = ((const float4*)(W + (size_t)(kc + r) * FOUT))[q];
        }
        __syncthreads();
#pragma unroll
        for (int k = 0; k < 32; k += 4) {
            float4 a4[4];
#pragma unroll
            for (int r = 0; r < 4; r++) a4[r] = *(const float4*)&As[rg * 4 + r][k];
#pragma unroll
            for (int kk = 0; kk < 4; kk++) {
                unsigned long long wp[NP2];
                if constexpr (CP == 4) {
                    float4 w4 = *(const float4*)&Ws[k + kk][lane * 4];
                    wp[0] = pack2_(w4.x, w4.y);
                    wp[1] = pack2_(w4.z, w4.w);
                } else {
                    float2 w2 = *(const float2*)&Ws[k + kk][lane * 2];
                    wp[0] = pack2_(w2.x, w2.y);
                }
#pragma unroll
                for (int r = 0; r < 4; r++) {
                    unsigned long long av2 = dup2_((&a4[r].x)[kk]);
                    if ((kk & 1) == 0) {
#pragma unroll
                        for (int c = 0; c < NP2; c++) accA2[r][c] = fma2_(av2, wp[c], accA2[r][c]);
                    } else {
#pragma unroll
                        for (int c = 0; c < NP2; c++) accB2[r][c] = fma2_(av2, wp[c], accB2[r][c]);
                    }
                }
            }
        }
        __syncthreads();
    }

#pragma unroll
    for (int r = 0; r < 4; r++) {
        int row = m0 + rg * 4 + r;
#pragma unroll
        for (int cp = 0; cp < NP2; cp++) {
            float aLo, aHi, bLo, bHi;
            unpack2_(accA2[r][cp], aLo, aHi);
            unpack2_(accB2[r][cp], bLo, bHi);
            float v0 = __fadd_rn(aLo, bLo);
            float v1 = __fadd_rn(aHi, bHi);
            int c0 = cp * 2, c1 = cp * 2 + 1;
            if (bias != nullptr) {
                v0 = __fadd_rn(v0, bias[lane * CP + c0]);
                v1 = __fadd_rn(v1, bias[lane * CP + c1]);
            }
            if (act == 1) { v0 = fmaxf(v0, 0.0f); v1 = fmaxf(v1, 0.0f); }
            else if (act == 2) { v0 = xla_tanhf(v0); v1 = xla_tanhf(v1); }
            C[(size_t)row * FOUT + lane * CP + c0] = v0;
            C[(size_t)row * FOUT + lane * CP + c1] = v1;
        }
    }
}

// ---------------- TF32 tensor-core matmul (tolerance-bound paths) ----------------
template<int FOUT>
__global__ void tmm_kernel(const float* __restrict__ A, const float* __restrict__ W,
                           const float* __restrict__ bias, float* __restrict__ C, int act) {
    constexpr int NT = FOUT / 16;
    __shared__ float As[64][36];
    __shared__ float Ws[32][FOUT + 4];
    const int tid = threadIdx.x;
    const int warp = tid >> 5, lane = tid & 31;
    const int wr = warp & 3;
    const int wc = warp >> 2;
    const int m0 = blockIdx.x * 64;
    const int mrow = wr * 16;
    const int n0 = wc * (FOUT / 2);
    const int gq = lane >> 2, tg = lane & 3;

    float acc[NT][4];
#pragma unroll
    for (int t = 0; t < NT; t++)
#pragma unroll
        for (int i = 0; i < 4; i++) acc[t][i] = 0.0f;

    for (int kc = 0; kc < 128; kc += 32) {
        for (int i = tid; i < 512; i += 256) {
            int r = i >> 3, q = i & 7;
            float4 v = *(const float4*)(A + (size_t)(m0 + r) * 128 + kc + q * 4);
            As[r][q * 4 + 0] = v.x; As[r][q * 4 + 1] = v.y;
            As[r][q * 4 + 2] = v.z; As[r][q * 4 + 3] = v.w;
        }
        for (int i = tid; i < 32 * FOUT / 4; i += 256) {
            int r = i / (FOUT / 4), q = i % (FOUT / 4);
            float4 v = *(const float4*)(W + (size_t)(kc + r) * FOUT + q * 4);
            Ws[r][q * 4 + 0] = v.x; Ws[r][q * 4 + 1] = v.y;
            Ws[r][q * 4 + 2] = v.z; Ws[r][q * 4 + 3] = v.w;
        }
        __syncthreads();
#pragma unroll
        for (int k8 = 0; k8 < 32; k8 += 8) {
            unsigned a0 = tf32_(As[mrow + gq][k8 + tg]);
            unsigned a1 = tf32_(As[mrow + gq + 8][k8 + tg]);
            unsigned a2 = tf32_(As[mrow + gq][k8 + tg + 4]);
            unsigned a3 = tf32_(As[mrow + gq + 8][k8 + tg + 4]);
#pragma unroll
            for (int t = 0; t < NT; t++) {
                int nb = n0 + t * 8;
                unsigned b0 = tf32_(Ws[k8 + tg][nb + gq]);
                unsigned b1 = tf32_(Ws[k8 + tg + 4][nb + gq]);
                asm volatile(
                    "mma.sync.aligned.m16n8k8.row.col.f32.tf32.tf32.f32 "
                    "{%0,%1,%2,%3}, {%4,%5,%6,%7}, {%8,%9}, {%0,%1,%2,%3};"
                    : "+f"(acc[t][0]), "+f"(acc[t][1]), "+f"(acc[t][2]), "+f"(acc[t][3])
                    : "r"(a0), "r"(a1), "r"(a2), "r"(a3), "r"(b0), "r"(b1));
            }
        }
        __syncthreads();
    }

#pragma unroll
    for (int t = 0; t < NT; t++) {
        int nb = n0 + t * 8 + 2 * tg;
        int r0 = m0 + mrow + gq;
        float v0 = acc[t][0], v1 = acc[t][1], v2 = acc[t][2], v3 = acc[t][3];
        if (bias != nullptr) {
            float b0v = bias[nb], b1v = bias[nb + 1];
            v0 += b0v; v1 += b1v; v2 += b0v; v3 += b1v;
        }
        if (act == 1) {
            v0 = fmaxf(v0, 0.f); v1 = fmaxf(v1, 0.f);
            v2 = fmaxf(v2, 0.f); v3 = fmaxf(v3, 0.f);
        }
        C[(size_t)r0 * FOUT + nb]     = v0;
        C[(size_t)r0 * FOUT + nb + 1] = v1;
        C[(size_t)(r0 + 8) * FOUT + nb]     = v2;
        C[(size_t)(r0 + 8) * FOUT + nb + 1] = v3;
    }
}

// ---------------- GCN aggregation (f32x2-packed; per-feature chains bitwise) ----------------
__global__ void agg_kernel(const float* __restrict__ t, const int* __restrict__ row,
                           const int* __restrict__ csr, const float* __restrict__ dinv,
                           const float* __restrict__ invd, const float* __restrict__ bias,
                           float* __restrict__ out, int n, int act) {
    int v = (blockIdx.x * blockDim.x + threadIdx.x) >> 5;
    int lane = threadIdx.x & 31;
    if (v >= n) return;
    int beg = row[v], end = row[v + 1];
    float dv = dinv[v], iv = invd[v];
    unsigned long long axy = 0ull, azw = 0ull;
#pragma unroll 4
    for (int j = beg; j < end; j++) {
        int s = __ldg(&csr[j]);
        float w = __fmul_rn(__ldg(&dinv[s]), dv);
        unsigned long long w2 = dup2_(w);
        float4 h = *(const float4*)&t[(size_t)s * 128 + lane * 4];
        axy = add2_(axy, mul2_(pack2_(h.x, h.y), w2));
        azw = add2_(azw, mul2_(pack2_(h.z, h.w), w2));
    }
    float ax, ay, az, aw;
    unpack2_(axy, ax, ay);
    unpack2_(azw, az, aw);
    float4 tv = *(const float4*)&t[(size_t)v * 128 + lane * 4];
    float4 b4 = *(const float4*)&bias[lane * 4];
    float o0 = __fadd_rn(__fadd_rn(ax, __fmul_rn(tv.x, iv)), b4.x);
    float o1 = __fadd_rn(__fadd_rn(ay, __fmul_rn(tv.y, iv)), b4.y);
    float o2 = __fadd_rn(__fadd_rn(az, __fmul_rn(tv.z, iv)), b4.z);
    float o3 = __fadd_rn(__fadd_rn(aw, __fmul_rn(tv.w, iv)), b4.w);
    if (act == 1) { o0 = fmaxf(o0, 0.f); o1 = fmaxf(o1, 0.f); o2 = fmaxf(o2, 0.f); o3 = fmaxf(o3, 0.f); }
    else if (act == 2) { o0 = xla_tanhf(o0); o1 = xla_tanhf(o1); o2 = xla_tanhf(o2); o3 = xla_tanhf(o3); }
    *(float4*)&out[(size_t)v * 128 + lane * 4] = make_float4(o0, o1, o2, o3);
}

__global__ void dot128_kernel(const float* __restrict__ A, const float* __restrict__ w,
                              float* __restrict__ out, int M) {
    int v = blockIdx.x * blockDim.x + threadIdx.x;
    if (v >= M) return;
    const float* a = A + (size_t)v * 128;
    float l0 = 0.f, l1 = 0.f, l2 = 0.f, l3 = 0.f;
#pragma unroll 8
    for (int k = 0; k < 128; k += 4) {
        l0 = fmaf(a[k],     __ldg(&w[k]),     l0);
        l1 = fmaf(a[k + 1], __ldg(&w[k + 1]), l1);
        l2 = fmaf(a[k + 2], __ldg(&w[k + 2]), l2);
        l3 = fmaf(a[k + 3], __ldg(&w[k + 3]), l3);
    }
    out[v] = __fadd_rn(__fadd_rn(l0, l2), __fadd_rn(l1, l3));
}

__global__ void scoreagg_kernel(const float* __restrict__ lin, const int* __restrict__ row,
                                const int* __restrict__ csr, const float* __restrict__ dinv,
                                const float* __restrict__ invd, const float* __restrict__ bias,
                                float* __restrict__ score, int n) {
    int v = blockIdx.x * blockDim.x + threadIdx.x;
    if (v >= n) return;
    int beg = row[v], end = row[v + 1];
    float dv = dinv[v];
    float acc = 0.0f;
    for (int j = beg; j < end; j++) {
        int s = csr[j];
        float w = __fmul_rn(dinv[s], dv);
        acc = __fadd_rn(acc, __fmul_rn(lin[s], w));
    }
    score[v] = __fadd_rn(__fadd_rn(acc, __fmul_rn(lin[v], invd[v])), bias[0]);
}

template<int NP>
__global__ void topk_kernel(const float* __restrict__ score, int* __restrict__ perm,
                            int* __restrict__ pos, int kkeep, float thr_rel) {
    __shared__ float ss[NP];
    __shared__ int   si[NP];
    int b = blockIdx.x, tid = threadIdx.x;
    for (int i = tid; i < NP; i += blockDim.x) {
        ss[i] = score[b * NP + i];
        si[i] = i;
        pos[b * NP + i] = -1;
    }
    __syncthreads();
    for (int k = 2; k <= NP; k <<= 1) {
        for (int j = k >> 1; j > 0; j >>= 1) {
            for (int i = tid; i < NP; i += blockDim.x) {
                int ixj = i ^ j;
                if (ixj > i) {
                    float sa = ss[i], sb = ss[ixj];
                    int ia = si[i], ib = si[ixj];
                    bool b_first = (sb > sa) || (sb == sa && ib < ia);
                    bool a_first = (sa > sb) || (sa == sb && ia < ib);
                    bool sw = ((i & k) == 0) ? b_first : a_first;
                    if (sw) { ss[i] = sb; ss[ixj] = sa; si[i] = ib; si[ixj] = ia; }
                }
            }
            __syncthreads();
        }
    }
    if (tid == 0 && thr_rel > 0.0f) {
        for (int pass = 0; pass < 6; pass++) {
            bool any = false;
            for (int p = 0; p < NP - 1; p++) {
                float a = ss[p], c = ss[p + 1];
                if (a > c) {
                    float gap = __fadd_rn(a, -c);
                    float thr = thr_rel * fmaxf(fabsf(a), fabsf(c));
                    if (gap <= thr && si[p] > si[p + 1]) {
                        ss[p] = c; ss[p + 1] = a;
                        int t2 = si[p]; si[p] = si[p + 1]; si[p + 1] = t2;
                        any = true;
                    }
                }
            }
            if (!any) break;
        }
    }
    __syncthreads();
    for (int i = tid; i < kkeep; i += blockDim.x) {
        int g = b * NP + si[i];
        perm[b * kkeep + i] = g;
        pos[g] = b * kkeep + i;
    }
}

// fused gate+unpool level 1: xp1 (compacted) and xout in one h1 pass
__global__ void unpoolgate1_kernel(const float* __restrict__ h, const float* __restrict__ score,
                                   const int* __restrict__ pos, float* __restrict__ xp,
                                   float* __restrict__ out) {
    int gid = blockIdx.x * blockDim.x + threadIdx.x;
    if (gid >= NN * 128) return;
    int v = gid >> 7, c = gid & 127;
    int j = pos[v];
    float val = 0.0f;
    if (j >= 0) {
        val = __fmul_rn(h[gid], xla_tanhf(score[v]));
        xp[(size_t)j * 128 + c] = val;
    }
    out[gid] = val;
}

// fused gate+double-unpool level 2: xp2 (compacted) and xoutF in one pass
__global__ void unpoolgate2_kernel(const float* __restrict__ h2, const float* __restrict__ score2,
                                   float* __restrict__ xp2, float* __restrict__ out) {
    int gid = blockIdx.x * blockDim.x + threadIdx.x;
    if (gid >= NN * 128) return;
    int v = gid >> 7, c = gid & 127;
    int p1 = g_pos1[v];
    float val = 0.0f;
    if (p1 >= 0) {
        int p2 = g_pos2[p1];
        if (p2 >= 0) {
            val = __fmul_rn(h2[(size_t)p1 * 128 + c], xla_tanhf(score2[p1]));
            xp2[(size_t)p2 * 128 + c] = val;
        }
    }
    out[gid] = val;
}

__global__ void pool_stats_kernel(const float* __restrict__ xp, float* __restrict__ g, int kk) {
    int b = blockIdx.x, c = threadIdx.x;
    float mx = -3.402823466e38f, sm = 0.f;
    const float* base = xp + (size_t)b * kk * 128;
    for (int r = 0; r < kk; r++) {
        float v = base[(size_t)r * 128 + c];
        mx = fmaxf(mx, v);
        sm = __fadd_rn(sm, v);
    }
    g[b * 256 + c] = mx;
    g[b * 256 + 128 + c] = __fdiv_rn(sm, (float)kk);
}

__global__ void gather_kernel(const int* __restrict__ perm, float* __restrict__ og,
                              float* __restrict__ op, int cnt) {
    int j = blockIdx.x * blockDim.x + threadIdx.x;
    if (j >= cnt) return;
    int v = perm[j];
    og[j] = g_deggt[v];
    op[j] = g_xdeg[v];
}

__global__ void mlp641_kernel(const float* __restrict__ in, const float* __restrict__ w,
                              const float* __restrict__ bptr, float* __restrict__ out, int M) {
    int v = blockIdx.x * blockDim.x + threadIdx.x;
    if (v >= M) return;
    const float* a = in + (size_t)v * 64;
    float l0 = 0.f, l1 = 0.f, l2 = 0.f, l3 = 0.f;
#pragma unroll
    for (int k = 0; k < 64; k += 4) {
        l0 = fmaf(a[k],     __ldg(&w[k]),     l0);
        l1 = fmaf(a[k + 1], __ldg(&w[k + 1]), l1);
        l2 = fmaf(a[k + 2], __ldg(&w[k + 2]), l2);
        l3 = fmaf(a[k + 3], __ldg(&w[k + 3]), l3);
    }
    float acc = __fadd_rn(__fadd_rn(l0, l2), __fadd_rn(l1, l3));
    acc = __fadd_rn(acc, bptr[0]);
    out[v] = fmaxf(acc, 0.f);
}

__global__ void head_kernel(const float* __restrict__ wl1, const float* __restrict__ bl1,
                            const float* __restrict__ wl2, const float* __restrict__ bl2,
                            const float* __restrict__ wl3, const float* __restrict__ bl3,
                            float* __restrict__ ocls) {
    __shared__ float gg[256];
    __shared__ float ga[128];
    __shared__ float gb[64];
    int b = blockIdx.x, t = threadIdx.x;
    gg[t]       = g_g1[b * 256 + t]       + g_g2[b * 256 + t];
    gg[t + 128] = g_g1[b * 256 + 128 + t] + g_g2[b * 256 + 128 + t];
    __syncthreads();
    float acc = 0.0f;
    for (int k = 0; k < 256; k++) acc = fmaf(gg[k], wl1[k * 128 + t], acc);
    ga[t] = fmaxf(acc + bl1[t], 0.f);
    __syncthreads();
    if (t < 64) {
        float a2 = 0.0f;
        for (int k = 0; k < 128; k++) a2 = fmaf(ga[k], wl2[k * 64 + t], a2);
        gb[t] = fmaxf(a2 + bl2[t], 0.f);
    }
    __syncthreads();
    if (t < 10) {
        float a3 = 0.0f;
        for (int k = 0; k < 64; k++) a3 = fmaf(gb[k], wl3[k * 10 + t], a3);
        ocls[b * 10 + t] = a3 + bl3[t];
    }
}

// ---------------- host ----------------
static void* devp(const void* sym) {
    void* p = nullptr;
    cudaGetSymbolAddress(&p, sym);
    return p;
}

extern "C" void kernel_launch(void* const* d_in, const int* in_sizes, int n_in,
                              void* d_out, int out_size) {
    const float* x     = (const float*)d_in[0];
    const int*   esrc  = (const int*)d_in[1];
    const int*   edst  = (const int*)d_in[2];
    const float* w_c1 = (const float*)d_in[3];  const float* b_c1 = (const float*)d_in[4];
    const float* w_c2 = (const float*)d_in[5];  const float* b_c2 = (const float*)d_in[6];
    const float* w_c3 = (const float*)d_in[7];  const float* b_c3 = (const float*)d_in[8];
    const float* w_c4 = (const float*)d_in[9];  const float* b_c4 = (const float*)d_in[10];
    const float* w_c5 = (const float*)d_in[11]; const float* b_c5 = (const float*)d_in[12];
    const float* w_p1 = (const float*)d_in[13]; const float* b_p1 = (const float*)d_in[14];
    const float* w_p2 = (const float*)d_in[15]; const float* b_p2 = (const float*)d_in[16];
    const float* w_l1 = (const float*)d_in[17]; const float* b_l1 = (const float*)d_in[18];
    const float* w_l2 = (const float*)d_in[19]; const float* b_l2 = (const float*)d_in[20];
    const float* w_l3 = (const float*)d_in[21]; const float* b_l3 = (const float*)d_in[22];
    const float* w_l4 = (const float*)d_in[23]; const float* b_l4 = (const float*)d_in[24];
    const float* w_l5 = (const float*)d_in[25]; const float* b_l5 = (const float*)d_in[26];
    const float* w_l6 = (const float*)d_in[27]; const float* b_l6 = (const float*)d_in[28];

    float* out = (float*)d_out;
    float* o_cls  = out;
    float* o_dec1 = out + 320;
    float* o_dec2 = o_dec1 + (size_t)NN * FH;
    float* o_dgt1 = o_dec2 + (size_t)NN * FH;
    float* o_dpr1 = o_dgt1 + BK1;
    float* o_dgt2 = o_dpr1 + BK1;
    float* o_dpr2 = o_dgt2 + BK2;

    float* p_t     = (float*)devp(g_t);
    float* p_h1    = (float*)devp(g_h1);
    float* p_a     = (float*)devp(g_a);
    float* p_bf    = (float*)devp(g_bf);
    float* p_xout  = (float*)devp(g_xout);
    float* p_xoutF = (float*)devp(g_xoutF);
    float* p_mA    = (float*)devp(g_mA);
    float* p_mB    = (float*)devp(g_mB);
    float* p_xp1   = (float*)devp(g_xp1);
    float* p_t2    = (float*)devp(g_t2);
    float* p_h2    = (float*)devp(g_h2);
    float* p_xp2   = (float*)devp(g_xp2);
    float* p_lin   = (float*)devp(g_lin);
    float* p_sc1   = (float*)devp(g_sc1);
    float* p_sc2   = (float*)devp(g_sc2);
    float* p_xdeg  = (float*)devp(g_xdeg);
    float* p_dinv1 = (float*)devp(g_dinv1);
    float* p_invd1 = (float*)devp(g_invd1);
    float* p_dinv2 = (float*)devp(g_dinv2);
    float* p_invd2 = (float*)devp(g_invd2);
    int*   p_cntD  = (int*)devp(g_cntD);
    int*   p_row1  = (int*)devp(g_row1);
    int*   p_csr1  = (int*)devp(g_csr1);
    int*   p_cnt2  = (int*)devp(g_cnt2);
    int*   p_row2  = (int*)devp(g_row2);
    int*   p_csr2  = (int*)devp(g_csr2);
    int*   p_perm1 = (int*)devp(g_perm1);
    int*   p_pos1  = (int*)devp(g_pos1);
    int*   p_perm2 = (int*)devp(g_perm2);
    int*   p_pos2  = (int*)devp(g_pos2);
    float* p_g1    = (float*)devp(g_g1);
    float* p_g2    = (float*)devp(g_g2);

    // ---- level 1 prep ----
    zero_counts_kernel<<<NN / 256, 256>>>();
    count_kernel<<<EE / 256, 256>>>(esrc, edst);
    mm_kernel<128><<<NN / 32, 256>>>(x, w_c1, nullptr, p_t, 0);
    scan_p1_kernel<<<SCAN_NB, 256>>>(p_cntD, NN);
    scan_p3_kernel<<<SCAN_NB, 256>>>(p_cntD, p_row1, NN, 1);
    fill1_kernel<<<EE / 256, 256>>>(esrc, edst);
    sortmap_kernel<<<NN / 8, 256>>>(p_row1, p_csr1, esrc, NN, 1);
    agg_kernel<<<NN / 8, 256>>>(p_t, p_row1, p_csr1, p_dinv1, p_invd1, b_c1, p_h1, NN, 1);

    // ---- SAGPool level 1 (separate kernels; bitwise) ----
    dot128_kernel<<<NN / 256, 256>>>(p_h1, w_p1, p_lin, NN);
    scoreagg_kernel<<<NN / 256, 256>>>(p_lin, p_row1, p_csr1, p_dinv1, p_invd1, b_p1, p_sc1, NN);
    topk_kernel<1024><<<BB, 512>>>(p_sc1, p_perm1, p_pos1, K1c, 6e-7f);
    unpoolgate1_kernel<<<(NN * 128) / 256, 256>>>(p_h1, p_sc1, p_pos1, p_xp1, p_xout);

    // ---- decoder 1 -> o_dec1 (tf32) ----
    tmm_kernel<128><<<NN / 64, 256>>>(p_xout, w_c3, nullptr, p_t, 0);
    agg_kernel<<<NN / 8, 256>>>(p_t, p_row1, p_csr1, p_dinv1, p_invd1, b_c3, p_a, NN, 2);
    tmm_kernel<128><<<NN / 64, 256>>>(p_a, w_c4, nullptr, p_t, 0);
    agg_kernel<<<NN / 8, 256>>>(p_t, p_row1, p_csr1, p_dinv1, p_invd1, b_c4, p_bf, NN, 2);
    tmm_kernel<128><<<NN / 64, 256>>>(p_bf, w_c5, nullptr, p_t, 0);
    agg_kernel<<<NN / 8, 256>>>(p_t, p_row1, p_csr1, p_dinv1, p_invd1, b_c5, o_dec1, NN, 0);

    // ---- degree mlp (tf32) ----
    tmm_kernel<128><<<NN / 64, 256>>>(p_xout, w_l4, b_l4, p_mA, 1);
    tmm_kernel<64><<<NN / 64, 256>>>(p_mA, w_l5, b_l5, p_mB, 1);
    mlp641_kernel<<<NN / 256, 256>>>(p_mB, w_l6, b_l6, p_xdeg, NN);
    gather_kernel<<<BK1 / 256, 256>>>(p_perm1, o_dgt1, o_dpr1, BK1);
    pool_stats_kernel<<<BB, 128>>>(p_xp1, p_g1, K1c);

    // ---- level 2 graph ----
    count2_kernel<<<EE / 256, 256>>>(esrc, edst);
    scan_p1_kernel<<<SCAN_NB, 256>>>(p_cnt2, BK1);
    scan_p3_kernel<<<SCAN_NB, 256>>>(p_cnt2, p_row2, BK1, 2);
    fill2_kernel<<<EE / 256, 256>>>(esrc, edst);
    sortmap_kernel<<<BK1 / 8, 256>>>(p_row2, p_csr2, esrc, BK1, 2);

    // h2 = relu(gcn(xp1, w_c2)) (bitwise)
    mm_kernel<128><<<BK1 / 32, 256>>>(p_xp1, w_c2, nullptr, p_t2, 0);
    agg_kernel<<<BK1 / 8, 256>>>(p_t2, p_row2, p_csr2, p_dinv2, p_invd2, b_c2, p_h2, BK1, 1);

    // ---- SAGPool level 2 (separate kernels; bitwise, no near-tie canon) ----
    dot128_kernel<<<BK1 / 256, 256>>>(p_h2, w_p2, p_lin, BK1);
    scoreagg_kernel<<<BK1 / 256, 256>>>(p_lin, p_row2, p_csr2, p_dinv2, p_invd2, b_p2, p_sc2, BK1);
    topk_kernel<512><<<BB, 512>>>(p_sc2, p_perm2, p_pos2, K2c, 0.0f);
    unpoolgate2_kernel<<<(NN * 128) / 256, 256>>>(p_h2, p_sc2, p_xp2, p_xoutF);
    gather_kernel<<<BK2 / 256, 256>>>(p_perm2, o_dgt2, o_dpr2, BK2);
    pool_stats_kernel<<<BB, 128>>>(p_xp2, p_g2, K2c);

    // ---- decoder 2 -> o_dec2 (tf32) ----
    tmm_kernel<128><<<NN / 64, 256>>>(p_xoutF, w_c3, nullptr, p_t, 0);
    agg_kernel<<<NN / 8, 256>>>(p_t, p_row1, p_csr1, p_dinv1, p_invd1, b_c3, p_a, NN, 2);
    tmm_kernel<128><<<NN / 64, 256>>>(p_a, w_c4, nullptr, p_t, 0);
    agg_kernel<<<NN / 8, 256>>>(p_t, p_row1, p_csr1, p_dinv1, p_invd1, b_c4, p_bf, NN, 2);
    tmm_kernel<128><<<NN / 64, 256>>>(p_bf, w_c5, nullptr, p_t, 0);
    agg_kernel<<<NN / 8, 256>>>(p_t, p_row1, p_csr1, p_dinv1, p_invd1, b_c5, o_dec2, NN, 0);

    // ---- classification head ----
    head_kernel<<<BB, 128>>>(w_l1, b_l1, w_l2, b_l2, w_l3, b_l3, o_cls);
}